// round 9
// baseline (speedup 1.0000x reference)
#include <cuda_runtime.h>
#include <cstdint>

#define NB    4096     // batch
#define NO    256      // orbitals
#define NF    128      // fermions
#define HID   512      // hidden
#define LDA   132      // padded row stride: 528B, 16B-aligned; 132 mod 32 = 4
#define NTHR  256
#define PB    8        // LU panel width
#define NPAN  (NF/PB)  // 16 panels

// Shared layout (floats): A | idx | perm | pcopy | wcnt(8) | sJ(8)
#define SMEM_FLOATS (NF*LDA + NF + NF + NF + 8 + 8)
#define SMEM_BYTES  (SMEM_FLOATS * 4)

__device__ __forceinline__ void fma4(float4& a, float m, const float4& u) {
    a.x -= m * u.x; a.y -= m * u.y; a.z -= m * u.z; a.w -= m * u.w;
}

// Warp-synchronous panel factorization (warp 0 only). Factors panel columns
// [kp, kp+PB) over logical rows >= kp, virtual pivoting via perm.
__device__ __forceinline__ void factor_panel(float* __restrict__ A,
                                             int*   __restrict__ perm,
                                             int kp, int lane, float& logabs)
{
    #pragma unroll
    for (int kk = 0; kk < PB; kk++) {
        const int k = kp + kk;
        float v = -1.0f; int vi = k;
        #pragma unroll
        for (int j = 0; j < 4; j++) {
            const int i = lane + 32*j;
            if (i >= k) {
                const float a = fabsf(A[perm[i]*LDA + k]);
                if (a > v) { v = a; vi = i; }
            }
        }
        #pragma unroll
        for (int o = 16; o; o >>= 1) {
            const float ov = __shfl_xor_sync(0xffffffffu, v,  o);
            const int   oi = __shfl_xor_sync(0xffffffffu, vi, o);
            if (ov > v) { v = ov; vi = oi; }
        }
        int pk = 0; float inv = 0.0f;
        if (lane == 0) {
            if (vi != k) { int t = perm[k]; perm[k] = perm[vi]; perm[vi] = t; }
            pk = perm[k];
            const float piv = A[pk*LDA + k];
            logabs += __logf(fabsf(piv));
            inv = 1.0f / piv;
        }
        __syncwarp();
        pk  = __shfl_sync(0xffffffffu, pk,  0);
        inv = __shfl_sync(0xffffffffu, inv, 0);

        const float* prow = A + pk*LDA + kp;
        #pragma unroll
        for (int j = 0; j < 4; j++) {
            const int i = lane + 32*j;
            if (i > k) {
                float* row = A + perm[i]*LDA;
                const float m = row[k] * inv;
                row[k] = m;
                #pragma unroll
                for (int c = 0; c < PB; c++)
                    if (c > kk) row[kp + c] -= m * prow[c];
            }
        }
        __syncwarp();
    }
}

__global__ void __launch_bounds__(NTHR, 3)
lnjs_kernel(const float* __restrict__ n_in,
            const float* __restrict__ M_in,
            const float* __restrict__ W_in,
            const float* __restrict__ b_in,
            float* __restrict__ out)
{
    extern __shared__ float sm[];
    float* A     = sm;
    int*   idx   = (int*)(sm + NF*LDA);
    int*   perm  = idx + NF;
    int*   pcopy = perm + NF;
    int*   wcnt  = pcopy + NF;
    float* sJ    = (float*)(wcnt + 8);

    const int s    = blockIdx.x;
    const int tid  = threadIdx.x;
    const int lane = tid & 31;
    const int wid  = tid >> 5;

    // ---------- 1. occupied indices via ballot prefix (NO == NTHR == 256) ----------
    const float nv = n_in[s*NO + tid];
    const bool occ = nv > 0.5f;
    const unsigned mask = __ballot_sync(0xffffffffu, occ);
    const int rank = __popc(mask & ((1u << lane) - 1u));
    if (lane == 0) wcnt[wid] = __popc(mask);
    __syncthreads();
    {
        int off = 0;
        #pragma unroll
        for (int w = 0; w < 8; w++) if (w < wid) off += wcnt[w];
        if (occ) idx[off + rank] = tid;
    }
    if (tid < NF) perm[tid] = tid;
    __syncthreads();

    // ---------- 2. Jastrow ----------
    float acc0 = b_in[tid];
    float acc1 = b_in[tid + 256];
    #pragma unroll 4
    for (int i = 0; i < NF; i++) {
        const float* wr = W_in + (size_t)idx[i] * HID;
        acc0 += wr[tid];
        acc1 += wr[tid + 256];
    }
    float jl = tanhf(acc0) + tanhf(acc1);
    #pragma unroll
    for (int o = 16; o; o >>= 1) jl += __shfl_xor_sync(0xffffffffu, jl, o);
    if (lane == 0) sJ[wid] = jl;

    // ---------- 3. load A = M[idx] into smem (float4) ----------
    #pragma unroll
    for (int e = tid; e < NF*32; e += NTHR) {
        const int r  = e >> 5;
        const int c4 = e & 31;
        ((float4*)(A + r*LDA))[c4] = ((const float4*)(M_in + (size_t)idx[r]*NF))[c4];
    }
    __syncthreads();

    // ---------- 4. blocked LU, partial pivoting, lookahead-1, vectorized ----------
    float logabs = 0.0f;   // warp 0 lane 0 accumulates

    if (wid == 0) factor_panel(A, perm, 0, lane, logabs);
    __syncthreads();

    for (int p = 0; p < NPAN - 1; p++) {
        const int kp = p * PB;
        const int pe = kp + PB;

        // ======== phase A (all 8 warps) ========
        if (pe + tid < NF) pcopy[pe + tid] = perm[pe + tid];

        // strip update: cols [pe, pe+8), rows logical >= pe.
        // lane&1 -> which half (float4) of the strip; lane>>1 -> row sub (0..15)
        {
            const int ch = (lane & 1) * 4;   // 0 or 4
            const int rs = lane >> 1;        // 0..15
            // TRSM: u4[k2] = U[kp+k2][pe+ch .. +4)
            float4 u4[PB];
            #pragma unroll
            for (int k2 = 0; k2 < PB; k2++) {
                const float* ur = A + perm[kp + k2]*LDA;
                float4 val = *(const float4*)(ur + pe + ch);
                #pragma unroll
                for (int j2 = 0; j2 < PB; j2++)
                    if (j2 < k2) fma4(val, ur[kp + j2], u4[j2]);
                u4[k2] = val;
            }
            const int i = pe + (wid << 4) + rs;   // 8 warps x 16 rows = 128 slots
            if (i < NF) {
                float* row = A + perm[i]*LDA;
                const float4 l0 = *(const float4*)(row + kp);
                const float4 l1 = *(const float4*)(row + kp + 4);
                float4 a = *(const float4*)(row + pe + ch);
                fma4(a, l0.x, u4[0]); fma4(a, l0.y, u4[1]);
                fma4(a, l0.z, u4[2]); fma4(a, l0.w, u4[3]);
                fma4(a, l1.x, u4[4]); fma4(a, l1.y, u4[5]);
                fma4(a, l1.z, u4[6]); fma4(a, l1.w, u4[7]);
                *(float4*)(row + pe + ch) = a;
            }
        }
        __syncthreads();

        // ======== phase B (concurrent, disjoint columns) ========
        if (wid == 0) {
            factor_panel(A, perm, pe, lane, logabs);
        } else {
            // wide trailing update: cols >= pe+8 (thread owns cols 4*lane..4*lane+3)
            const bool act = (4*lane >= pe + PB);
            // TRSM u4 build (all lanes; harmless reads for inactive lanes)
            float4 u4[PB];
            #pragma unroll
            for (int k2 = 0; k2 < PB; k2++) {
                const float* ur = A + perm[kp + k2]*LDA;
                float4 val = *(const float4*)(ur + 4*lane);
                #pragma unroll
                for (int j2 = 0; j2 < PB; j2++)
                    if (j2 < k2) fma4(val, ur[kp + j2], u4[j2]);
                u4[k2] = val;
            }
            for (int i = pe + (wid - 1); i < NF; i += 7) {
                float* row = A + pcopy[i]*LDA;
                const float4 l0 = *(const float4*)(row + kp);
                const float4 l1 = *(const float4*)(row + kp + 4);
                if (act) {
                    float4 a = *(const float4*)(row + 4*lane);
                    fma4(a, l0.x, u4[0]); fma4(a, l0.y, u4[1]);
                    fma4(a, l0.z, u4[2]); fma4(a, l0.w, u4[3]);
                    fma4(a, l1.x, u4[4]); fma4(a, l1.y, u4[5]);
                    fma4(a, l1.z, u4[6]); fma4(a, l1.w, u4[7]);
                    *(float4*)(row + 4*lane) = a;
                }
            }
        }
        __syncthreads();
    }

    // ---------- 5. combine & write real part of log psi ----------
    if (tid == 0) {
        float J = 0.0f;
        #pragma unroll
        for (int w = 0; w < 8; w++) J += sJ[w];
        out[s] = logabs + J;
    }
}

extern "C" void kernel_launch(void* const* d_in, const int* in_sizes, int n_in,
                              void* d_out, int out_size)
{
    // Identify inputs by element count (robust to metadata ordering):
    const float* n = nullptr;
    const float* M = nullptr;
    const float* W = nullptr;
    const float* b = nullptr;
    for (int i = 0; i < n_in; i++) {
        switch (in_sizes[i]) {
            case NB * NO:  n = (const float*)d_in[i]; break;
            case NO * NF:  M = (const float*)d_in[i]; break;
            case NO * HID: W = (const float*)d_in[i]; break;
            case HID:      b = (const float*)d_in[i]; break;
            default: break;
        }
    }
    float* out = (float*)d_out;   // (4096,) float32: real part of log psi

    cudaFuncSetAttribute(lnjs_kernel,
                         cudaFuncAttributeMaxDynamicSharedMemorySize,
                         SMEM_BYTES);

    lnjs_kernel<<<NB, NTHR, SMEM_BYTES>>>(n, M, W, b, out);
}